// round 6
// baseline (speedup 1.0000x reference)
#include <cuda_runtime.h>
#include <cstdint>
#include <cstddef>

#define Bsz 8
#define Cc  32
#define Oo  64
#define Hh  64
#define Ww  64
#define Kk  9

constexpr int OTILE = 8;
constexpr int SEG   = Ww * Kk;            // 576 floats per (o,c,h)
constexpr int WTILE = OTILE * SEG;        // 4608 floats per c
constexpr int XROWS = 3;
constexpr int XCOLP = 72;
constexpr int XTILE = Bsz * XROWS * XCOLP;
constexpr int SMEM_BYTES = (2 * WTILE + 2 * XTILE) * 4;  // 50688 B -> 4 CTAs/SM
constexpr int WC_STRIDE = Hh * SEG;
constexpr int XC_STRIDE = Hh * Ww;

typedef unsigned long long ull;

__device__ __forceinline__ void cp16(float* dst_smem, const float* src, int sz) {
    uint32_t a = (uint32_t)__cvta_generic_to_shared(dst_smem);
    asm volatile("cp.async.cg.shared.global [%0], [%1], 16, %2;"
                 :: "r"(a), "l"(src), "r"(sz));
}

__device__ __forceinline__ ull pack2(float lo, float hi) {
    ull r;
    asm("mov.b64 %0, {%1, %2};" : "=l"(r) : "f"(lo), "f"(hi));
    return r;
}
__device__ __forceinline__ void unpack2(float& lo, float& hi, ull v) {
    asm("mov.b64 {%0, %1}, %2;" : "=f"(lo), "=f"(hi) : "l"(v));
}
// packed dual fp32 FMA: d = a*b + d (elementwise on both 32-bit halves)
__device__ __forceinline__ void fma2(ull& d, ull a, ull b) {
    asm("fma.rn.f32x2 %0, %1, %2, %0;" : "+l"(d) : "l"(a), "l"(b));
}

__global__ void __launch_bounds__(128, 4)
lc2d_kernel(const float* __restrict__ x,
            const float* __restrict__ wt,
            float* __restrict__ out)
{
    extern __shared__ float smem[];
    float* wsm = smem;                    // [2][WTILE]
    float* xsm = smem + 2 * WTILE;        // [2][XTILE]

    const int tx = threadIdx.x;           // 128 threads
    const int w  = tx & 63;
    const int oq = tx >> 6;               // 0..1
    const int h  = blockIdx.x;
    const int ob = blockIdx.y * OTILE;
    const int o0 = ob + oq * 4;

    // one-time halo zeros (cols 3 and 68 of every row, both buffers)
    if (tx < 96) {
        int bufsel = tx / 48;
        int t      = tx - bufsel * 48;
        int b      = t / 6;
        int q      = t - b * 6;
        int r      = q >> 1;
        int side   = q & 1;
        xsm[bufsel * XTILE + (b * XROWS + r) * XCOLP + (side ? 68 : 3)] = 0.f;
    }

    // ---- loop-invariant staging descriptors (marching gmem offsets) ----
    int wgo[9], wso[9];
    #pragma unroll
    for (int i = 0; i < 9; i++) {
        int idx = tx + i * 128;
        int seg = idx / 144;
        int pos = idx - seg * 144;
        wgo[i] = (((ob + seg) * Cc) * Hh + h) * SEG + pos * 4;
        wso[i] = seg * SEG + pos * 4;
    }
    int xgo[3], xso[3], xsz[3];
    #pragma unroll
    for (int i = 0; i < 3; i++) {
        int idx = tx + i * 128;
        int b   = idx / 48;
        int rem = idx - b * 48;
        int r   = rem >> 4;
        int j   = rem & 15;
        int grow = h - 1 + r;
        xsz[i]  = (grow >= 0 && grow < Hh) ? 16 : 0;
        int gr  = grow < 0 ? 0 : (grow > Hh - 1 ? Hh - 1 : grow);
        xgo[i]  = ((b * Cc) * Hh + gr) * Ww + j * 4;
        xso[i]  = (b * XROWS + r) * XCOLP + 4 + j * 4;
    }

    // packed accumulators: [o][batch-pair], halves = batches 2bp, 2bp+1
    ull acc2[4][4];
    #pragma unroll
    for (int oo = 0; oo < 4; oo++)
        #pragma unroll
        for (int bp = 0; bp < 4; bp++)
            acc2[oo][bp] = 0ull;

    auto stage = [&](int buf) {
        float* wb = wsm + buf * WTILE;
        #pragma unroll
        for (int i = 0; i < 9; i++) {
            cp16(wb + wso[i], wt + wgo[i], 16);
            wgo[i] += WC_STRIDE;
        }
        float* xb = xsm + buf * XTILE;
        #pragma unroll
        for (int i = 0; i < 3; i++) {
            cp16(xb + xso[i], x + xgo[i], xsz[i]);
            xgo[i] += XC_STRIDE;
        }
    };

    // depth-2 prologue
    stage(0);
    asm volatile("cp.async.commit_group;");
    stage(1);
    asm volatile("cp.async.commit_group;");

    for (int c = 0; c < Cc; c++) {
        const int cur = c & 1;
        asm volatile("cp.async.wait_group 1;");
        __syncthreads();                       // stage(c) visible

        const float* wb = wsm + cur * WTILE + oq * 4 * SEG + w * Kk;
        const float* xb = xsm + cur * XTILE + 3 + w;

        // process kernel in 3 k-rows to keep packed weights at 24 regs
        #pragma unroll
        for (int r = 0; r < 3; r++) {
            // packed (duplicated) weights for this row: 4 o x 3 k
            ull wr2[4][3];
            #pragma unroll
            for (int oo = 0; oo < 4; oo++)
                #pragma unroll
                for (int kk = 0; kk < 3; kk++) {
                    float f = wb[oo * SEG + r * 3 + kk];
                    wr2[oo][kk] = pack2(f, f);
                }

            #pragma unroll
            for (int bp = 0; bp < 4; bp++) {
                const float* xlo = xb + (2 * bp)     * (XROWS * XCOLP) + r * XCOLP;
                const float* xhi = xb + (2 * bp + 1) * (XROWS * XCOLP) + r * XCOLP;
                ull xv2[3];
                #pragma unroll
                for (int kk = 0; kk < 3; kk++)
                    xv2[kk] = pack2(xlo[kk], xhi[kk]);

                #pragma unroll
                for (int oo = 0; oo < 4; oo++)
                    #pragma unroll
                    for (int kk = 0; kk < 3; kk++)
                        fma2(acc2[oo][bp], wr2[oo][kk], xv2[kk]);
            }
        }

        __syncthreads();                       // all reads of buf `cur` done
        if (c + 2 < Cc)
            stage(cur);                        // refill just-consumed buffer
        asm volatile("cp.async.commit_group;");
    }

    // epilogue: unpack batch pairs, coalesced stores
    float* op = out + ((size_t)o0 * Hh + h) * Ww + w;
    #pragma unroll
    for (int bp = 0; bp < 4; bp++)
        #pragma unroll
        for (int oo = 0; oo < 4; oo++) {
            float lo, hi;
            unpack2(lo, hi, acc2[oo][bp]);
            op[(size_t)((2 * bp)     * Oo + oo) * (Hh * Ww)] = lo;
            op[(size_t)((2 * bp + 1) * Oo + oo) * (Hh * Ww)] = hi;
        }
}

extern "C" void kernel_launch(void* const* d_in, const int* in_sizes, int n_in,
                              void* d_out, int out_size)
{
    const float* x  = (const float*)d_in[0];
    const float* wt = (const float*)d_in[1];
    float* out      = (float*)d_out;

    cudaFuncSetAttribute(lc2d_kernel,
                         cudaFuncAttributeMaxDynamicSharedMemorySize, SMEM_BYTES);

    dim3 grid(Hh, Oo / OTILE);   // 64 x 8 = 512 blocks of 128 threads
    lc2d_kernel<<<grid, 128, SMEM_BYTES>>>(x, wt, out);
}